// round 6
// baseline (speedup 1.0000x reference)
#include <cuda_runtime.h>

#define HDIM 10
#define MM   41
#define SMAX 512

typedef unsigned long long u64;

// Packed tables (repacked every launch; deterministic).
__device__ float4 g_W1p[SMAX * HDIM];   // [s*10+2p]=ws, [s*10+2p+1]=wd (S/D halved weights)
__device__ float4 g_meta[SMAX];         // (Cx/2, Cy/2, -Cy/2, Cx/2)
__device__ int    g_pk[SMAX];           // (c+m) | (c+m+n)<<8 | (c+n)<<16
__device__ float4 g_W2p[MM * HDIM];

__device__ __forceinline__ u64 pk2(float a, float b) {
    u64 r; asm("mov.b64 %0,{%1,%2};" : "=l"(r) : "f"(a), "f"(b)); return r;
}
__device__ __forceinline__ void up2(u64 v, float& a, float& b) {
    asm("mov.b64 {%0,%1},%2;" : "=f"(a), "=f"(b) : "l"(v));
}
__device__ __forceinline__ void fma2(u64& d, u64 a, u64 b) {
    asm("fma.rn.f32x2 %0,%1,%2,%0;" : "+l"(d) : "l"(a), "l"(b));
}
__device__ __forceinline__ void add2(u64& d, u64 a) {
    asm("add.rn.f32x2 %0,%1,%0;" : "+l"(d) : "l"(a));
}

__global__ void repack_kernel(const float2* __restrict__ W1,
                              const float2* __restrict__ W2,
                              const float2* __restrict__ C,
                              const int* __restrict__ m_idx,
                              const int* __restrict__ n_idx,
                              int S) {
    int t = blockIdx.x * blockDim.x + threadIdx.x;
    if (t < S) {
#pragma unroll
        for (int p = 0; p < 5; p++) {
            float2 a0 = W1[((2 * p) * 2 + 0) * S + t];
            float2 a1 = W1[((2 * p) * 2 + 1) * S + t];
            float2 b0c = W1[((2 * p + 1) * 2 + 0) * S + t];
            float2 b1c = W1[((2 * p + 1) * 2 + 1) * S + t];
            g_W1p[t * 10 + 2 * p] = make_float4(0.5f * (a0.x + a1.x), 0.5f * (b0c.x + b1c.x),
                                                0.5f * (a0.y + a1.y), 0.5f * (b0c.y + b1c.y));
            g_W1p[t * 10 + 2 * p + 1] = make_float4(0.5f * (a0.x - a1.x), 0.5f * (b0c.x - b1c.x),
                                                    0.5f * (a0.y - a1.y), 0.5f * (b0c.y - b1c.y));
        }
        float2 cc = C[t];
        const int c = MM / 2;
        int m = m_idx[t], n = n_idx[t];
        g_pk[t] = (c + m) | ((c + m + n) << 8) | ((c + n) << 16);
        g_meta[t] = make_float4(0.5f * cc.x, 0.5f * cc.y, -0.5f * cc.y, 0.5f * cc.x);
    }
    if (t < MM) {
#pragma unroll
        for (int p = 0; p < 5; p++) {
            float2 a0 = W2[((2 * p) * 2 + 0) * MM + t];
            float2 a1 = W2[((2 * p) * 2 + 1) * MM + t];
            float2 b0c = W2[((2 * p + 1) * 2 + 0) * MM + t];
            float2 b1c = W2[((2 * p + 1) * 2 + 1) * MM + t];
            g_W2p[t * 10 + 2 * p] = make_float4(0.5f * (a0.x + a1.x), 0.5f * (b0c.x + b1c.x),
                                                0.5f * (a0.y + a1.y), 0.5f * (b0c.y + b1c.y));
            g_W2p[t * 10 + 2 * p + 1] = make_float4(0.5f * (a0.x - a1.x), 0.5f * (b0c.x - b1c.x),
                                                    0.5f * (a0.y - a1.y), 0.5f * (b0c.y - b1c.y));
        }
    }
}

// Block = 32 batch elements, 4 warps; lane == local batch element.
// Reduction buffer overlays E_sh (E dead by then; center symbol saved to regs).
__global__ __launch_bounds__(128, 4)
void eq_main(const float4* __restrict__ x,      // [B][41] (E0r,E0i,E1r,E1i)
             const float* __restrict__ task,    // [B][4]
             const float2* __restrict__ b1,     // [10]
             const float2* __restrict__ b2,     // [10]
             float4* __restrict__ out,          // [B]
             int S) {
    __shared__ u64 red[2][44][32];              // 22.5 KB; first 21 KB doubles as E_sh
    __shared__ float4 meta_sh[SMAX];            // 8 KB  (Cx,Cy | -Cy,Cx) halved
    __shared__ int pk_sh[SMAX];                 // 2 KB

    float4* E_sh = (float4*)red;                // [32][41], stride 41 (odd, conflict-free)

    const int lane = threadIdx.x & 31;
    const int warp = threadIdx.x >> 5;
    const int tid = threadIdx.x;
    const int b0 = blockIdx.x * 32;

    for (int bl = warp; bl < 32; bl += 4)
        for (int k = lane; k < MM; k += 32)
            E_sh[bl * 41 + k] = x[(size_t)(b0 + bl) * MM + k];
    for (int t = tid; t < S; t += 128) {
        meta_sh[t] = g_meta[t];
        pk_sh[t] = g_pk[t];
    }
    __syncthreads();

    const float4* Eb = &E_sh[lane * 41];

    // acc layout: [0..4]=Sx, [5..9]=Sy, [10..14]=Dx, [15..19]=Dy
    u64 aA[20];
    u64 aPS = 0ull, aPD = 0ull;
#pragma unroll
    for (int i = 0; i < 20; i++) aA[i] = 0ull;

    const int chunk = (S + 3) >> 2;
    const int s_lo = warp * chunk;
    const int s_hi = (s_lo + chunk < S) ? (s_lo + chunk) : S;

#pragma unroll 2
    for (int s = s_lo; s < s_hi; s++) {
        const int pk = pk_sh[s];
        const ulonglong2 mc = *(const ulonglong2*)&meta_sh[s];  // (Cx,Cy) | (-Cy,Cx)
        float4 Em  = Eb[pk & 255];
        float4 Emn = Eb[(pk >> 8) & 255];
        float4 En  = Eb[(pk >> 16) & 255];
        float Asx = Em.x * Emn.x + Em.y * Emn.y + Em.z * Emn.z + Em.w * Emn.w;
        float Asy = Em.y * Emn.x - Em.x * Emn.y + Em.w * Emn.z - Em.z * Emn.w;
        float Ensx = En.x + En.z, Ensy = En.y + En.w;
        float Endx = En.x - En.z, Endy = En.y - En.w;
        float Fsx = Asx * Ensx - Asy * Ensy, Fsy = Asx * Ensy + Asy * Ensx;
        float Fdx = Asx * Endx - Asy * Endy, Fdy = Asx * Endy + Asy * Endx;

        u64 Fsxb = pk2(Fsx, Fsx), Fsyb = pk2(Fsy, Fsy), Fsynb = pk2(-Fsy, -Fsy);
        u64 Fdxb = pk2(Fdx, Fdx), Fdyb = pk2(Fdy, Fdy), Fdynb = pk2(-Fdy, -Fdy);

        fma2(aPS, mc.x, Fsxb); fma2(aPS, mc.y, Fsyb);
        fma2(aPD, mc.x, Fdxb); fma2(aPD, mc.y, Fdyb);

        const ulonglong2* wr = (const ulonglong2*)&g_W1p[s * 10];
#pragma unroll
        for (int p = 0; p < 5; p++) {
            ulonglong2 us = wr[2 * p];
            ulonglong2 ud = wr[2 * p + 1];
            fma2(aA[p],      us.x, Fsxb); fma2(aA[p],      us.y, Fsynb);
            fma2(aA[5 + p],  us.x, Fsyb); fma2(aA[5 + p],  us.y, Fsxb);
            fma2(aA[10 + p], ud.x, Fdxb); fma2(aA[10 + p], ud.y, Fdynb);
            fma2(aA[15 + p], ud.x, Fdyb); fma2(aA[15 + p], ud.y, Fdxb);
        }
    }

    // ---- W2 conv (S/D form) ----
    u64 aB[20];
#pragma unroll
    for (int i = 0; i < 20; i++) aB[i] = 0ull;

    for (int k = warp; k < MM; k += 4) {
        float4 Ek = Eb[k];
        float Esx = Ek.x + Ek.z, Esy = Ek.y + Ek.w;
        float Edx = Ek.x - Ek.z, Edy = Ek.y - Ek.w;
        u64 Esxb = pk2(Esx, Esx), Esyb = pk2(Esy, Esy), Esynb = pk2(-Esy, -Esy);
        u64 Edxb = pk2(Edx, Edx), Edyb = pk2(Edy, Edy), Edynb = pk2(-Edy, -Edy);
        const ulonglong2* wr = (const ulonglong2*)&g_W2p[k * 10];
#pragma unroll
        for (int p = 0; p < 5; p++) {
            ulonglong2 us = wr[2 * p];
            ulonglong2 ud = wr[2 * p + 1];
            fma2(aB[p],      us.x, Esxb); fma2(aB[p],      us.y, Esynb);
            fma2(aB[5 + p],  us.x, Esyb); fma2(aB[5 + p],  us.y, Esxb);
            fma2(aB[10 + p], ud.x, Edxb); fma2(aB[10 + p], ud.y, Edynb);
            fma2(aB[15 + p], ud.x, Edyb); fma2(aB[15 + p], ud.y, Edxb);
        }
    }

    // Save what the epilogue needs from E before the overlay is clobbered.
    float4 Ec = Eb[MM / 2];
    __syncthreads();   // all warps done reading E_sh

    // ---- 4->2->1 tree reduction (red overlays E_sh) ----
    if (warp >= 2) {
        u64* q = &red[warp - 2][0][lane];
#pragma unroll
        for (int i = 0; i < 20; i++) { q[i * 32] = aA[i]; q[(20 + i) * 32] = aB[i]; }
        q[40 * 32] = aPS; q[41 * 32] = aPD;
    }
    __syncthreads();
    if (warp < 2) {
        const u64* q = &red[warp][0][lane];
#pragma unroll
        for (int i = 0; i < 20; i++) { add2(aA[i], q[i * 32]); add2(aB[i], q[(20 + i) * 32]); }
        add2(aPS, q[40 * 32]); add2(aPD, q[41 * 32]);
    }
    __syncthreads();
    if (warp == 1) {
        u64* q = &red[0][0][lane];
#pragma unroll
        for (int i = 0; i < 20; i++) { q[i * 32] = aA[i]; q[(20 + i) * 32] = aB[i]; }
        q[40 * 32] = aPS; q[41 * 32] = aPD;
    }
    __syncthreads();

    if (warp == 0) {
        const u64* q = &red[0][0][lane];
#pragma unroll
        for (int i = 0; i < 20; i++) { add2(aA[i], q[i * 32]); add2(aB[i], q[(20 + i) * 32]); }
        add2(aPS, q[40 * 32]); add2(aPD, q[41 * 32]);

        float PSx, PSy, PDx, PDy;
        up2(aPS, PSx, PSy);
        up2(aPD, PDx, PDy);
        float P0x = PSx + PDx, P0y = PSy + PDy;
        float P1x = PSx - PDx, P1y = PSy - PDy;

        float p = exp10f(task[(size_t)(b0 + lane) * 4] * 0.1f) * 0.5f;
        float o0x = Ec.x + p * P0x, o0y = Ec.y + p * P0y;
        float o1x = Ec.z + p * P1x, o1y = Ec.w + p * P1y;

        float t0x = 0.f, t0y = 0.f, t1x = 0.f, t1y = 0.f;
#pragma unroll
        for (int pp = 0; pp < 5; pp++) {
            float Sx[2], Sy[2], Dx[2], Dy[2];
            float bSx[2], bSy[2], bDx[2], bDy[2];
            up2(aA[pp],      Sx[0], Sx[1]);
            up2(aA[5 + pp],  Sy[0], Sy[1]);
            up2(aA[10 + pp], Dx[0], Dx[1]);
            up2(aA[15 + pp], Dy[0], Dy[1]);
            up2(aB[pp],      bSx[0], bSx[1]);
            up2(aB[5 + pp],  bSy[0], bSy[1]);
            up2(aB[10 + pp], bDx[0], bDx[1]);
            up2(aB[15 + pp], bDy[0], bDy[1]);
#pragma unroll
            for (int h = 0; h < 2; h++) {
                int o = 2 * pp + h;
                float2 c1 = b1[o], c2 = b2[o];
                float a0x = Sx[h] + Dx[h] + c1.x, a0y = Sy[h] + Dy[h] + c1.y;
                float a1x = Sx[h] - Dx[h] + c1.x, a1y = Sy[h] - Dy[h] + c1.y;
                float bx0 = bSx[h] + bDx[h] + c2.x, by0 = bSy[h] + bDy[h] + c2.y;
                float bx1 = bSx[h] - bDx[h] + c2.x, by1 = bSy[h] - bDy[h] + c2.y;
                float n0 = bx0 * bx0 + by0 * by0;
                float sx0 = bx0 * bx0 - by0 * by0, sy0 = 2.f * bx0 * by0;
                t0x += a0x * n0 + a0x * sx0 + a0y * sy0;
                t0y += a0y * n0 + a0x * sy0 - a0y * sx0;
                float n1 = bx1 * bx1 + by1 * by1;
                float sx1 = bx1 * bx1 - by1 * by1, sy1 = 2.f * bx1 * by1;
                t1x += a1x * n1 + a1x * sx1 + a1y * sy1;
                t1y += a1y * n1 + a1x * sy1 - a1y * sx1;
            }
        }
        float sc = 3.1622776601683794e-5f * p * p;   // (1e-4/sqrt(HDIM)) * P^2
        out[b0 + lane] = make_float4(o0x + sc * t0x, o0y + sc * t0y,
                                     o1x + sc * t1x, o1y + sc * t1y);
    }
}

extern "C" void kernel_launch(void* const* d_in, const int* in_sizes, int n_in,
                              void* d_out, int out_size) {
    const float4* x    = (const float4*)d_in[0];
    const float*  task = (const float*)d_in[1];
    const float2* C    = (const float2*)d_in[2];
    const float2* W1   = (const float2*)d_in[3];
    const float2* b1   = (const float2*)d_in[4];
    const float2* W2   = (const float2*)d_in[5];
    const float2* b2   = (const float2*)d_in[6];
    const int* m_idx   = (const int*)d_in[7];
    const int* n_idx   = (const int*)d_in[8];

    int S = in_sizes[8];
    int B = in_sizes[1] / 4;

    repack_kernel<<<(S + 127) / 128, 128>>>(W1, W2, C, m_idx, n_idx, S);
    eq_main<<<B / 32, 128>>>(x, task, b1, b2, (float4*)d_out, S);
}

// round 7
// speedup vs baseline: 1.0041x; 1.0041x over previous
#include <cuda_runtime.h>

#define HDIM 10
#define MM   41
#define SMAX 512

// Packed tables (rewritten every launch; deterministic).
// g_W1p[s*10+j] = (Wsx_j, Wsy_j, Wdx_j, Wdy_j): S/D halved weights for output j.
__device__ float4 g_W1p[SMAX * HDIM];
__device__ float2 g_C[SMAX];            // (Cx/2, Cy/2)
__device__ int    g_pk[SMAX];           // (c+m) | (c+m+n)<<8 | (c+n)<<16
__device__ float4 g_W2p[MM * HDIM];

__global__ void repack_kernel(const float2* __restrict__ W1,
                              const float2* __restrict__ W2,
                              const float2* __restrict__ C,
                              const int* __restrict__ m_idx,
                              const int* __restrict__ n_idx,
                              int S) {
    int t = blockIdx.x * blockDim.x + threadIdx.x;
    if (t < S) {
#pragma unroll
        for (int j = 0; j < HDIM; j++) {
            float2 a0 = W1[(j * 2 + 0) * S + t];
            float2 a1 = W1[(j * 2 + 1) * S + t];
            g_W1p[t * HDIM + j] = make_float4(0.5f * (a0.x + a1.x), 0.5f * (a0.y + a1.y),
                                              0.5f * (a0.x - a1.x), 0.5f * (a0.y - a1.y));
        }
        float2 cc = C[t];
        g_C[t] = make_float2(0.5f * cc.x, 0.5f * cc.y);
        const int c = MM / 2;
        int m = m_idx[t], n = n_idx[t];
        g_pk[t] = (c + m) | ((c + m + n) << 8) | ((c + n) << 16);
    }
    if (t < MM) {
#pragma unroll
        for (int j = 0; j < HDIM; j++) {
            float2 a0 = W2[(j * 2 + 0) * MM + t];
            float2 a1 = W2[(j * 2 + 1) * MM + t];
            g_W2p[t * HDIM + j] = make_float4(0.5f * (a0.x + a1.x), 0.5f * (a0.y + a1.y),
                                              0.5f * (a0.x - a1.x), 0.5f * (a0.y - a1.y));
        }
    }
}

// Block = 32 batch elements, 4 warps; lane == local batch element.
__global__ __launch_bounds__(128, 4)
void eq_main(const float4* __restrict__ x,      // [B][41] (E0r,E0i,E1r,E1i)
             const float* __restrict__ task,    // [B][4]
             const float2* __restrict__ b1,     // [10]
             const float2* __restrict__ b2,     // [10]
             float4* __restrict__ out,          // [B]
             int S) {
    __shared__ float2 red[2][44][32];           // 22.5 KB; start doubles as E_sh (21 KB)
    __shared__ float2 C_sh[SMAX];               // 4 KB
    __shared__ int pk_sh[SMAX];                 // 2 KB

    float4* E_sh = (float4*)red;                // [32][41] stride 41

    const int lane = threadIdx.x & 31;
    const int warp = threadIdx.x >> 5;
    const int tid = threadIdx.x;
    const int b0 = blockIdx.x * 32;

    for (int bl = warp; bl < 32; bl += 4)
        for (int k = lane; k < MM; k += 32)
            E_sh[bl * 41 + k] = x[(size_t)(b0 + bl) * MM + k];
    for (int t = tid; t < S; t += 128) { C_sh[t] = g_C[t]; pk_sh[t] = g_pk[t]; }
    __syncthreads();

    const float4* Eb = &E_sh[lane * 41];

    float ASx[10], ASy[10], ADx[10], ADy[10];
    float PSx = 0.f, PSy = 0.f, PDx = 0.f, PDy = 0.f;
#pragma unroll
    for (int j = 0; j < 10; j++) { ASx[j] = ASy[j] = ADx[j] = ADy[j] = 0.f; }

    for (int s = warp; s < S; s += 4) {
        const int pk = pk_sh[s];
        const float2 cc = C_sh[s];
        float4 Em  = Eb[pk & 255];
        float4 Emn = Eb[(pk >> 8) & 255];
        float4 En  = Eb[(pk >> 16) & 255];
        // Asum = sum_p E[c+m,p]*conj(E[c+m+n,p])
        float Asx = Em.x * Emn.x + Em.y * Emn.y + Em.z * Emn.z + Em.w * Emn.w;
        float Asy = Em.y * Emn.x - Em.x * Emn.y + Em.w * Emn.z - Em.z * Emn.w;
        // Fs = As*(En0+En1), Fd = As*(En0-En1)
        float Ensx = En.x + En.z, Ensy = En.y + En.w;
        float Endx = En.x - En.z, Endy = En.y - En.w;
        float Fsx = Asx * Ensx - Asy * Ensy, Fsy = Asx * Ensy + Asy * Ensx;
        float Fdx = Asx * Endx - Asy * Endy, Fdy = Asx * Endy + Asy * Endx;
        float nFsy = -Fsy, nFdy = -Fdy;

        PSx += cc.x * Fsx + cc.y * nFsy;  PSy += cc.x * Fsy + cc.y * Fsx;
        PDx += cc.x * Fdx + cc.y * nFdy;  PDy += cc.x * Fdy + cc.y * Fdx;

        const float4* wr = &g_W1p[s * HDIM];
#pragma unroll
        for (int j = 0; j < 10; j++) {
            float4 w = wr[j];   // (Wsx, Wsy, Wdx, Wdy)
            ASx[j] += w.x * Fsx + w.y * nFsy;
            ASy[j] += w.x * Fsy + w.y * Fsx;
            ADx[j] += w.z * Fdx + w.w * nFdy;
            ADy[j] += w.z * Fdy + w.w * Fdx;
        }
    }

    // ---- W2 conv (S/D form) ----
    float BSx[10], BSy[10], BDx[10], BDy[10];
#pragma unroll
    for (int j = 0; j < 10; j++) { BSx[j] = BSy[j] = BDx[j] = BDy[j] = 0.f; }

    for (int k = warp; k < MM; k += 4) {
        float4 Ek = Eb[k];
        float Esx = Ek.x + Ek.z, Esy = Ek.y + Ek.w;
        float Edx = Ek.x - Ek.z, Edy = Ek.y - Ek.w;
        float nEsy = -Esy, nEdy = -Edy;
        const float4* wr = &g_W2p[k * HDIM];
#pragma unroll
        for (int j = 0; j < 10; j++) {
            float4 w = wr[j];
            BSx[j] += w.x * Esx + w.y * nEsy;
            BSy[j] += w.x * Esy + w.y * Esx;
            BDx[j] += w.z * Edx + w.w * nEdy;
            BDy[j] += w.z * Edy + w.w * Edx;
        }
    }

    float4 Ec = Eb[MM / 2];      // epilogue input, saved before overlay clobbers E
    __syncthreads();

    // ---- 4->2->1 tree reduction (red overlays E_sh) ----
    // entries: 0..9 (ASx,ASy), 10..19 (ADx,ADy), 20..29 (BSx,BSy), 30..39 (BDx,BDy), 40 PS, 41 PD
    if (warp >= 2) {
        float2* q = &red[warp - 2][0][lane];
#pragma unroll
        for (int j = 0; j < 10; j++) {
            q[j * 32] = make_float2(ASx[j], ASy[j]);
            q[(10 + j) * 32] = make_float2(ADx[j], ADy[j]);
            q[(20 + j) * 32] = make_float2(BSx[j], BSy[j]);
            q[(30 + j) * 32] = make_float2(BDx[j], BDy[j]);
        }
        q[40 * 32] = make_float2(PSx, PSy);
        q[41 * 32] = make_float2(PDx, PDy);
    }
    __syncthreads();
    if (warp < 2) {
        const float2* q = &red[warp][0][lane];
#pragma unroll
        for (int j = 0; j < 10; j++) {
            float2 v;
            v = q[j * 32];        ASx[j] += v.x; ASy[j] += v.y;
            v = q[(10 + j) * 32]; ADx[j] += v.x; ADy[j] += v.y;
            v = q[(20 + j) * 32]; BSx[j] += v.x; BSy[j] += v.y;
            v = q[(30 + j) * 32]; BDx[j] += v.x; BDy[j] += v.y;
        }
        float2 v = q[40 * 32]; PSx += v.x; PSy += v.y;
        v = q[41 * 32];        PDx += v.x; PDy += v.y;
    }
    __syncthreads();
    if (warp == 1) {
        float2* q = &red[0][0][lane];
#pragma unroll
        for (int j = 0; j < 10; j++) {
            q[j * 32] = make_float2(ASx[j], ASy[j]);
            q[(10 + j) * 32] = make_float2(ADx[j], ADy[j]);
            q[(20 + j) * 32] = make_float2(BSx[j], BSy[j]);
            q[(30 + j) * 32] = make_float2(BDx[j], BDy[j]);
        }
        q[40 * 32] = make_float2(PSx, PSy);
        q[41 * 32] = make_float2(PDx, PDy);
    }
    __syncthreads();

    if (warp == 0) {
        const float2* q = &red[0][0][lane];
#pragma unroll
        for (int j = 0; j < 10; j++) {
            float2 v;
            v = q[j * 32];        ASx[j] += v.x; ASy[j] += v.y;
            v = q[(10 + j) * 32]; ADx[j] += v.x; ADy[j] += v.y;
            v = q[(20 + j) * 32]; BSx[j] += v.x; BSy[j] += v.y;
            v = q[(30 + j) * 32]; BDx[j] += v.x; BDy[j] += v.y;
        }
        float2 v = q[40 * 32]; PSx += v.x; PSy += v.y;
        v = q[41 * 32];        PDx += v.x; PDy += v.y;

        float P0x = PSx + PDx, P0y = PSy + PDy;
        float P1x = PSx - PDx, P1y = PSy - PDy;

        float p = exp10f(task[(size_t)(b0 + lane) * 4] * 0.1f) * 0.5f;
        float o0x = Ec.x + p * P0x, o0y = Ec.y + p * P0y;
        float o1x = Ec.z + p * P1x, o1y = Ec.w + p * P1y;

        float t0x = 0.f, t0y = 0.f, t1x = 0.f, t1y = 0.f;
#pragma unroll
        for (int j = 0; j < 10; j++) {
            float2 c1 = b1[j], c2 = b2[j];
            float a0x = ASx[j] + ADx[j] + c1.x, a0y = ASy[j] + ADy[j] + c1.y;
            float a1x = ASx[j] - ADx[j] + c1.x, a1y = ASy[j] - ADy[j] + c1.y;
            float bx0 = BSx[j] + BDx[j] + c2.x, by0 = BSy[j] + BDy[j] + c2.y;
            float bx1 = BSx[j] - BDx[j] + c2.x, by1 = BSy[j] - BDy[j] + c2.y;
            float n0 = bx0 * bx0 + by0 * by0;
            float sx0 = bx0 * bx0 - by0 * by0, sy0 = 2.f * bx0 * by0;
            t0x += a0x * n0 + a0x * sx0 + a0y * sy0;
            t0y += a0y * n0 + a0x * sy0 - a0y * sx0;
            float n1 = bx1 * bx1 + by1 * by1;
            float sx1 = bx1 * bx1 - by1 * by1, sy1 = 2.f * bx1 * by1;
            t1x += a1x * n1 + a1x * sx1 + a1y * sy1;
            t1y += a1y * n1 + a1x * sy1 - a1y * sx1;
        }
        float sc = 3.1622776601683794e-5f * p * p;   // (1e-4/sqrt(HDIM)) * P^2
        out[b0 + lane] = make_float4(o0x + sc * t0x, o0y + sc * t0y,
                                     o1x + sc * t1x, o1y + sc * t1y);
    }
}

extern "C" void kernel_launch(void* const* d_in, const int* in_sizes, int n_in,
                              void* d_out, int out_size) {
    const float4* x    = (const float4*)d_in[0];
    const float*  task = (const float*)d_in[1];
    const float2* C    = (const float2*)d_in[2];
    const float2* W1   = (const float2*)d_in[3];
    const float2* b1   = (const float2*)d_in[4];
    const float2* W2   = (const float2*)d_in[5];
    const float2* b2   = (const float2*)d_in[6];
    const int* m_idx   = (const int*)d_in[7];
    const int* n_idx   = (const int*)d_in[8];

    int S = in_sizes[8];
    int B = in_sizes[1] / 4;

    repack_kernel<<<(S + 127) / 128, 128>>>(W1, W2, C, m_idx, n_idx, S);
    eq_main<<<B / 32, 128>>>(x, task, b1, b2, (float4*)d_out, S);
}

// round 8
// speedup vs baseline: 1.4096x; 1.4038x over previous
#include <cuda_runtime.h>
#include <cuda_fp16.h>
#include <cstdint>

#define MM    41
#define SPAD  448          // padded F-type u slots (S <= 448)
#define UPAD  512          // total u slots; K = 4*UPAD = 2048
#define NTILE 10           // n-tiles of 8 -> N = 80
#define KTILE 128          // k-tiles of 16
#define NCHUNK 8           // K chunks of 256 (64 u)

__device__ uint4  g_Bfrag[NTILE * (KTILE / 2) * 32];   // per-lane B fragments
__device__ float4 g_meta[SPAD];                        // (Cx/2, Cy/2, pk_bits, 0)

__device__ __forceinline__ uint32_t pack_h2(float lo, float hi) {
    uint32_t r;
    asm("cvt.rn.f16x2.f32 %0, %1, %2;" : "=r"(r) : "f"(hi), "f"(lo));
    return r;
}
__device__ __forceinline__ void mma16816(float* d, const uint32_t* a, const uint32_t* b) {
    asm volatile(
        "mma.sync.aligned.m16n8k16.row.col.f32.f16.f16.f32 "
        "{%0,%1,%2,%3}, {%4,%5,%6,%7}, {%8,%9}, {%0,%1,%2,%3};"
        : "+f"(d[0]), "+f"(d[1]), "+f"(d[2]), "+f"(d[3])
        : "r"(a[0]), "r"(a[1]), "r"(a[2]), "r"(a[3]), "r"(b[0]), "r"(b[1]));
}

// Weight value at (k row, col) of the big B matrix [K=2048][80].
// cols 0..39: A-GEMM (W1, S/D halved); cols 40..79: Bm (W2). k = 4u+e.
__device__ float bwval(int k, int col, int S,
                       const float2* __restrict__ W1, const float2* __restrict__ W2) {
    int u = k >> 2, e = k & 3;
    bool isB = col >= 40;
    int cl = isB ? col - 40 : col;
    int j = cl >> 2, c = cl & 3;
    float2 w0, w1;
    if (!isB) {
        if (u >= S) return 0.f;
        w0 = W1[(j * 2 + 0) * S + u];
        w1 = W1[(j * 2 + 1) * S + u];
    } else {
        int m = u - SPAD;
        if (m < 0 || m >= MM) return 0.f;
        w0 = W2[(j * 2 + 0) * MM + m];
        w1 = W2[(j * 2 + 1) * MM + m];
    }
    float sx = 0.5f * (w0.x + w1.x), sy = 0.5f * (w0.y + w1.y);
    float dx = 0.5f * (w0.x - w1.x), dy = 0.5f * (w0.y - w1.y);
    if (c == 0) return e == 0 ? sx : (e == 1 ? -sy : 0.f);   // Sx row
    if (c == 1) return e == 0 ? sy : (e == 1 ?  sx : 0.f);   // Sy row
    if (c == 2) return e == 2 ? dx : (e == 3 ? -dy : 0.f);   // Dx row
    return        e == 2 ? dy : (e == 3 ?  dx : 0.f);        // Dy row
}

__global__ void repack(const float2* __restrict__ W1, const float2* __restrict__ W2,
                       const float2* __restrict__ C,
                       const int* __restrict__ m_idx, const int* __restrict__ n_idx, int S) {
    int t = blockIdx.x * blockDim.x + threadIdx.x;
    if (t < SPAD) {
        if (t < S) {
            float2 cc = C[t];
            int m = m_idx[t], n = n_idx[t];
            int pk = (20 + m) | ((20 + m + n) << 8) | ((20 + n) << 16);
            g_meta[t] = make_float4(0.5f * cc.x, 0.5f * cc.y, __int_as_float(pk), 0.f);
        } else {
            g_meta[t] = make_float4(0.f, 0.f, __int_as_float(0), 0.f);
        }
    }
    if (t >= NTILE * (KTILE / 2) * 32) return;
    int lane = t & 31, ktp = (t >> 5) & 63, nt = t >> 11;
    int col = nt * 8 + (lane >> 2);
    int kr = (lane & 3) * 2;
    uint32_t r[4];
#pragma unroll
    for (int tt = 0; tt < 2; tt++) {
        int k0 = (2 * ktp + tt) * 16 + kr;
        r[2 * tt + 0] = pack_h2(bwval(k0,     col, S, W1, W2), bwval(k0 + 1, col, S, W1, W2));
        r[2 * tt + 1] = pack_h2(bwval(k0 + 8, col, S, W1, W2), bwval(k0 + 9, col, S, W1, W2));
    }
    g_Bfrag[t] = make_uint4(r[0], r[1], r[2], r[3]);
}

// Block = 32 batches, 4 warps (lane = batch). Features fp32 -> fp16 staged panel;
// GEMM on tensor cores; pbc stays fp32.
__global__ __launch_bounds__(128, 4)
void eq_main(const float4* __restrict__ x, const float* __restrict__ task,
             const float2* __restrict__ b1, const float2* __restrict__ b2,
             float4* __restrict__ out, int S) {
    __shared__ __align__(16) float4 E_sh[32 * 41];     // 21 KB; overlaid by Dout later
    __shared__ __align__(16) __half stage[32 * 264];   // A panel: 32 rows x 256 k (+8 pad)
    __shared__ float4 meta_sh[SPAD];                   // 7 KB
    __shared__ float4 pbcbuf[4][32];

    float* Dout = (float*)E_sh;                        // [32][88] f32 after overlay

    const int lane = threadIdx.x & 31;
    const int warp = threadIdx.x >> 5;
    const int tid = threadIdx.x;
    const int b0 = blockIdx.x * 32;

    for (int i = tid; i < 32 * MM; i += 128) {
        int bl = i / MM, k = i - bl * MM;
        E_sh[bl * 41 + k] = x[(size_t)(b0 + bl) * MM + k];
    }
    for (int i = tid; i < SPAD; i += 128) meta_sh[i] = g_meta[i];
    __syncthreads();

    const float4* Eb = &E_sh[lane * 41];

    float PSx = 0.f, PSy = 0.f, PDx = 0.f, PDy = 0.f;
    float d[5][4];
#pragma unroll
    for (int n = 0; n < 5; n++)
#pragma unroll
        for (int q = 0; q < 4; q++) d[n][q] = 0.f;

    const int mt = warp & 1, nb = 5 * (warp >> 1);
    const __half* Arow = stage + (mt * 16 + (lane >> 2)) * 264 + (lane & 3) * 2;

    for (int ch = 0; ch < NCHUNK; ch++) {
        // ---- feature phase: this warp's 16 u-slots ----
        int ubase = ch * 64 + warp * 16;
#pragma unroll 4
        for (int i = 0; i < 16; i++) {
            int u = ubase + i;
            uint2* dst = (uint2*)(stage + lane * 264 + 4 * (u - ch * 64));
            uint32_t h0 = 0, h1 = 0;
            if (u < SPAD) {
                float4 mtv = meta_sh[u];
                int pk = __float_as_int(mtv.z);
                float4 Em  = Eb[pk & 255];
                float4 Emn = Eb[(pk >> 8) & 255];
                float4 En  = Eb[(pk >> 16) & 255];
                float Asx = Em.x * Emn.x + Em.y * Emn.y + Em.z * Emn.z + Em.w * Emn.w;
                float Asy = Em.y * Emn.x - Em.x * Emn.y + Em.w * Emn.z - Em.z * Emn.w;
                float Ensx = En.x + En.z, Ensy = En.y + En.w;
                float Endx = En.x - En.z, Endy = En.y - En.w;
                float Fsx = Asx * Ensx - Asy * Ensy, Fsy = Asx * Ensy + Asy * Ensx;
                float Fdx = Asx * Endx - Asy * Endy, Fdy = Asx * Endy + Asy * Endx;
                PSx += mtv.x * Fsx - mtv.y * Fsy;  PSy += mtv.x * Fsy + mtv.y * Fsx;
                PDx += mtv.x * Fdx - mtv.y * Fdy;  PDy += mtv.x * Fdy + mtv.y * Fdx;
                h0 = pack_h2(Fsx, Fsy);
                h1 = pack_h2(Fdx, Fdy);
            } else if (u - SPAD < MM) {
                float4 Ek = Eb[u - SPAD];
                h0 = pack_h2(Ek.x + Ek.z, Ek.y + Ek.w);
                h1 = pack_h2(Ek.x - Ek.z, Ek.y - Ek.w);
            }
            *dst = make_uint2(h0, h1);
        }
        __syncthreads();

        // ---- mma phase: 16 k-tiles of this chunk ----
#pragma unroll 2
        for (int ktp = 0; ktp < 8; ktp++) {
            uint32_t a[2][4];
            const __half* pa = Arow + ktp * 32;
#pragma unroll
            for (int tt = 0; tt < 2; tt++) {
                const __half* q = pa + tt * 16;
                a[tt][0] = *(const uint32_t*)(q);
                a[tt][1] = *(const uint32_t*)(q + 8 * 264);
                a[tt][2] = *(const uint32_t*)(q + 8);
                a[tt][3] = *(const uint32_t*)(q + 8 * 264 + 8);
            }
            int kti = ch * 8 + ktp;
#pragma unroll
            for (int n = 0; n < 5; n++) {
                uint4 bb = g_Bfrag[(((nb + n) * (KTILE / 2)) + kti) * 32 + lane];
                uint32_t bA[2] = {bb.x, bb.y}, bB[2] = {bb.z, bb.w};
                mma16816(d[n], a[0], bA);
                mma16816(d[n], a[1], bB);
            }
        }
        __syncthreads();
    }

    // ---- epilogue ----
    float4 Ec;
    if (warp == 0) Ec = Eb[20];
    pbcbuf[warp][lane] = make_float4(PSx, PSy, PDx, PDy);
    __syncthreads();                      // E reads done; pbc visible

    // D fragments -> Dout [32][88] (overlays E_sh)
#pragma unroll
    for (int n = 0; n < 5; n++) {
        int colg = (nb + n) * 8 + (lane & 3) * 2;
        int r0 = mt * 16 + (lane >> 2);
        *(float2*)(Dout + r0 * 88 + colg)       = make_float2(d[n][0], d[n][1]);
        *(float2*)(Dout + (r0 + 8) * 88 + colg) = make_float2(d[n][2], d[n][3]);
    }
    __syncthreads();

    if (warp == 0) {
        float4 s0 = pbcbuf[0][lane], s1 = pbcbuf[1][lane];
        float4 s2 = pbcbuf[2][lane], s3 = pbcbuf[3][lane];
        float PSxT = s0.x + s1.x + s2.x + s3.x, PSyT = s0.y + s1.y + s2.y + s3.y;
        float PDxT = s0.z + s1.z + s2.z + s3.z, PDyT = s0.w + s1.w + s2.w + s3.w;
        float P0x = PSxT + PDxT, P0y = PSyT + PDyT;
        float P1x = PSxT - PDxT, P1y = PSyT - PDyT;

        float p = exp10f(task[(size_t)(b0 + lane) * 4] * 0.1f) * 0.5f;
        float o0x = Ec.x + p * P0x, o0y = Ec.y + p * P0y;
        float o1x = Ec.z + p * P1x, o1y = Ec.w + p * P1y;

        const float* row = Dout + lane * 88;
        float t0x = 0.f, t0y = 0.f, t1x = 0.f, t1y = 0.f;
#pragma unroll
        for (int j = 0; j < 10; j++) {
            float4 Av = *(const float4*)(row + 4 * j);        // ASx,ASy,ADx,ADy
            float4 Bv = *(const float4*)(row + 40 + 4 * j);   // BSx,BSy,BDx,BDy
            float2 c1 = b1[j], c2 = b2[j];
            float a0x = Av.x + Av.z + c1.x, a0y = Av.y + Av.w + c1.y;
            float a1x = Av.x - Av.z + c1.x, a1y = Av.y - Av.w + c1.y;
            float bx0 = Bv.x + Bv.z + c2.x, by0 = Bv.y + Bv.w + c2.y;
            float bx1 = Bv.x - Bv.z + c2.x, by1 = Bv.y - Bv.w + c2.y;
            float n0 = bx0 * bx0 + by0 * by0;
            float sx0 = bx0 * bx0 - by0 * by0, sy0 = 2.f * bx0 * by0;
            t0x += a0x * n0 + a0x * sx0 + a0y * sy0;
            t0y += a0y * n0 + a0x * sy0 - a0y * sx0;
            float n1 = bx1 * bx1 + by1 * by1;
            float sx1 = bx1 * bx1 - by1 * by1, sy1 = 2.f * bx1 * by1;
            t1x += a1x * n1 + a1x * sx1 + a1y * sy1;
            t1y += a1y * n1 + a1x * sy1 - a1y * sx1;
        }
        float sc = 3.1622776601683794e-5f * p * p;
        out[b0 + lane] = make_float4(o0x + sc * t0x, o0y + sc * t0y,
                                     o1x + sc * t1x, o1y + sc * t1y);
    }
}

extern "C" void kernel_launch(void* const* d_in, const int* in_sizes, int n_in,
                              void* d_out, int out_size) {
    const float4* x    = (const float4*)d_in[0];
    const float*  task = (const float*)d_in[1];
    const float2* C    = (const float2*)d_in[2];
    const float2* W1   = (const float2*)d_in[3];
    const float2* b1   = (const float2*)d_in[4];
    const float2* W2   = (const float2*)d_in[5];
    const float2* b2   = (const float2*)d_in[6];
    const int* m_idx   = (const int*)d_in[7];
    const int* n_idx   = (const int*)d_in[8];

    int S = in_sizes[8];
    int B = in_sizes[1] / 4;

    repack<<<(NTILE * (KTILE / 2) * 32 + 127) / 128, 128>>>(W1, W2, C, m_idx, n_idx, S);
    eq_main<<<B / 32, 128>>>(x, task, b1, b2, (float4*)d_out, S);
}